// round 1
// baseline (speedup 1.0000x reference)
#include <cuda_runtime.h>
#include <cuda_bf16.h>

// LIF spike scan: x [B=32, T=16, C=128, H=32, W=32] fp32 -> spikes same shape.
// Per spatial site (b,c,h,w), scan over t:
//   mem = mem * TAU + x_t
//   s   = (mem >= THRESH) ? 1 : 0
//   mem = (1 - s) * mem          (hard reset)
// Output s as float32.
//
// Memory-bound: 256 MiB in + 256 MiB out. Strategy: one thread owns one
// float4 spatial site; issue all 16 time-step loads up-front (independent),
// run the scan in registers, store all 16 results.

#define LIF_T      16
#define LIF_THRESH 0.5f
#define LIF_TAU    0.25f

__global__ __launch_bounds__(256) void lif_spike_kernel(
    const float4* __restrict__ x,   // [B, T, CHW/4] viewed as float4
    float4* __restrict__ out,
    int chw4,                        // C*H*W/4 = 32768
    int n_sites)                     // B * chw4
{
    int gid = blockIdx.x * blockDim.x + threadIdx.x;
    if (gid >= n_sites) return;

    int b  = gid / chw4;
    int sp = gid - b * chw4;

    // element offset of (b, t=0, sp) in float4 units
    long base = (long)b * (LIF_T * (long)chw4) + sp;

    // Front-batch all 16 loads (independent -> high MLP)
    float4 v[LIF_T];
#pragma unroll
    for (int t = 0; t < LIF_T; t++) {
        v[t] = x[base + (long)t * chw4];
    }

    // Sequential scan in registers, 4 lanes in parallel
    float4 mem = make_float4(0.f, 0.f, 0.f, 0.f);
#pragma unroll
    for (int t = 0; t < LIF_T; t++) {
        mem.x = fmaf(mem.x, LIF_TAU, v[t].x);
        mem.y = fmaf(mem.y, LIF_TAU, v[t].y);
        mem.z = fmaf(mem.z, LIF_TAU, v[t].z);
        mem.w = fmaf(mem.w, LIF_TAU, v[t].w);

        float sx = (mem.x >= LIF_THRESH) ? 1.f : 0.f;
        float sy = (mem.y >= LIF_THRESH) ? 1.f : 0.f;
        float sz = (mem.z >= LIF_THRESH) ? 1.f : 0.f;
        float sw = (mem.w >= LIF_THRESH) ? 1.f : 0.f;

        // hard reset
        mem.x = (sx != 0.f) ? 0.f : mem.x;
        mem.y = (sy != 0.f) ? 0.f : mem.y;
        mem.z = (sz != 0.f) ? 0.f : mem.z;
        mem.w = (sw != 0.f) ? 0.f : mem.w;

        // reuse v[] as output buffer
        v[t] = make_float4(sx, sy, sz, sw);
    }

#pragma unroll
    for (int t = 0; t < LIF_T; t++) {
        out[base + (long)t * chw4] = v[t];
    }
}

extern "C" void kernel_launch(void* const* d_in, const int* in_sizes, int n_in,
                              void* d_out, int out_size)
{
    const float* x = (const float*)d_in[0];
    float* out = (float*)d_out;

    // x: [32, 16, 128, 32, 32] => B=32, T=16, CHW=131072
    const int chw  = 128 * 32 * 32;     // 131072
    const int chw4 = chw / 4;           // 32768
    const int B    = in_sizes[0] / (LIF_T * chw);   // 32
    const int n_sites = B * chw4;       // 1,048,576

    const int threads = 256;
    const int blocks = (n_sites + threads - 1) / threads;

    lif_spike_kernel<<<blocks, threads>>>(
        (const float4*)x, (float4*)out, chw4, n_sites);
}